// round 13
// baseline (speedup 1.0000x reference)
#include <cuda_runtime.h>
#include <cuda_bf16.h>
#include <cstdint>

// ---------------------------------------------------------------------------
// MoE LoRA delta via mma.sync bf16 hi/lo split, smem-staged ldmatrix feeds.
//   x (T=8192, D=4096) f32, router_w (4, D), A (4,16,D), B (4,4096,16)
// P = Xh*Wh + Xh*Wl + Xl*Wh  (fp32 accum)  -> rel_err ~1e-5
// Pipeline:
//   prep  : A_ext = [A(64); router_w(4); 0(8)] + B -> bf16 hi/lo u32 (merged)
//   mid   : midp[split] = x @ A_ext^T  (sw-pipelined LDG + cp.async dbl-buf A)
//   comb  : gates (top-2 softmax * 4.0, shfl-shared) + gmid -> bf16 hi/lo
//   out   : out = gmid @ Bf^T  (128x64 CTA tile, 3 CTAs/SM, 32x32 per warp)
// ---------------------------------------------------------------------------

#define D_DIM   4096
#define O_DIM   4096
#define MAXT    8192
#define LSCALE  4.0f
#define KSPLIT  4
#define NROWS   72            // 64 lora + 4 router + 4 pad (9 n-tiles)
#define KU      (D_DIM / 2)   // u32 per A_ext row
#define S       72            // smem row stride in bf16 halves (144 B)

// ------------------------- device scratch (static) -------------------------
__device__ float    g_midp[KSPLIT][MAXT][NROWS];    // 9.4 MB
__device__ uint32_t g_Axh[NROWS][KU];               // 0.58 MB
__device__ uint32_t g_Axl[NROWS][KU];
__device__ uint32_t g_Bh[O_DIM][32];                // 0.5 MB
__device__ uint32_t g_Bl[O_DIM][32];
__device__ uint32_t g_Gh[MAXT][32];                 // 1 MB
__device__ uint32_t g_Gl[MAXT][32];

// ------------------------------ helpers ------------------------------------
static __device__ __forceinline__ uint32_t smem_u32(const void* p) {
    uint32_t a;
    asm("{ .reg .u64 t; cvta.to.shared.u64 t, %1; cvt.u32.u64 %0, t; }"
        : "=r"(a) : "l"(p));
    return a;
}
// fast split: hi = rn-bf16 pair (1 cvt), lo = rn-bf16 of exact residuals
static __device__ __forceinline__ void split2(float a, float b,
                                              uint32_t& hi, uint32_t& lo) {
    uint32_t h;
    asm("cvt.rn.bf16x2.f32 %0, %1, %2;" : "=r"(h) : "f"(b), "f"(a));
    float ahf = __uint_as_float(h << 16);
    float bhf = __uint_as_float(h & 0xFFFF0000u);
    float al = a - ahf;
    float bl = b - bhf;
    uint32_t l;
    asm("cvt.rn.bf16x2.f32 %0, %1, %2;" : "=r"(l) : "f"(bl), "f"(al));
    hi = h; lo = l;
}
static __device__ __forceinline__ void mma_bf16(float* c,
        uint32_t a0, uint32_t a1, uint32_t a2, uint32_t a3,
        uint32_t b0, uint32_t b1) {
    asm volatile(
        "mma.sync.aligned.m16n8k16.row.col.f32.bf16.bf16.f32 "
        "{%0,%1,%2,%3},{%4,%5,%6,%7},{%8,%9},{%0,%1,%2,%3};"
        : "+f"(c[0]), "+f"(c[1]), "+f"(c[2]), "+f"(c[3])
        : "r"(a0), "r"(a1), "r"(a2), "r"(a3), "r"(b0), "r"(b1));
}
#define LDSM_X4(d0, d1, d2, d3, a)                                           \
    asm volatile("ldmatrix.sync.aligned.m8n8.x4.shared.b16 {%0,%1,%2,%3}, [%4];" \
                 : "=r"(d0), "=r"(d1), "=r"(d2), "=r"(d3) : "r"(a))
#define LDSM_X2(d0, d1, a)                                                   \
    asm volatile("ldmatrix.sync.aligned.m8n8.x2.shared.b16 {%0,%1}, [%2];"   \
                 : "=r"(d0), "=r"(d1) : "r"(a))
#define CP_ASYNC16(dst, src)                                                 \
    asm volatile("cp.async.cg.shared.global [%0], [%1], 16;"                 \
                 :: "r"(dst), "l"(src) : "memory")
#define CP_COMMIT() asm volatile("cp.async.commit_group;" ::: "memory")
#define CP_WAIT1()  asm volatile("cp.async.wait_group 1;" ::: "memory")
#define CP_WAIT0()  asm volatile("cp.async.wait_group 0;" ::: "memory")

// ---------------------------------------------------------------------------
// prep (merged): blocks [0,288): A_ext -> g_Ax{h,l};  [288,304): B -> g_B{h,l}
// ---------------------------------------------------------------------------
__global__ __launch_bounds__(256)
void prep_kernel(const float* __restrict__ A, const float* __restrict__ rw,
                 const float* __restrict__ B)
{
    int bid = blockIdx.x;
    if (bid < 288) {
        int idx = bid * 256 + threadIdx.x;     // < NROWS * 1024
        int row = idx >> 10;
        int q   = idx & 1023;
        float4 v = make_float4(0.f, 0.f, 0.f, 0.f);
        if (row < 64)
            v = *reinterpret_cast<const float4*>(A + (size_t)row * D_DIM + q * 4);
        else if (row < 68)
            v = *reinterpret_cast<const float4*>(rw + (size_t)(row - 64) * D_DIM + q * 4);
        uint32_t h0, l0, h1, l1;
        split2(v.x, v.y, h0, l0);
        split2(v.z, v.w, h1, l1);
        *reinterpret_cast<uint2*>(&g_Axh[row][q * 2]) = make_uint2(h0, h1);
        *reinterpret_cast<uint2*>(&g_Axl[row][q * 2]) = make_uint2(l0, l1);
    } else {
        int o = (bid - 288) * 256 + threadIdx.x;
        if (o >= O_DIM) return;
        #pragma unroll
        for (int e = 0; e < 4; e++) {
            const float4* src = reinterpret_cast<const float4*>(
                B + ((size_t)e * O_DIM + o) * 16);
            #pragma unroll
            for (int i = 0; i < 4; i++) {
                float4 v = src[i];
                uint32_t h0, l0, h1, l1;
                split2(v.x, v.y, h0, l0);
                split2(v.z, v.w, h1, l1);
                *reinterpret_cast<uint2*>(&g_Bh[o][e * 8 + i * 2]) = make_uint2(h0, h1);
                *reinterpret_cast<uint2*>(&g_Bl[o][e * 8 + i * 2]) = make_uint2(l0, l1);
            }
        }
    }
}

// ---------------------------------------------------------------------------
// mid: midp[split] = x @ A_ext^T.  grid (T/128, KSPLIT), 256 thr.
//   x: LDG->reg for chunk c+1 issued before compute(c) (latency hidden).
//   A: cp.async into double-buffered smem (wait_group 1 keeps 1 in flight).
//   smem: xh|xl (128 x S) + 2 x (ah|al) (80 x S) = 82,944 B; 2 CTAs/SM.
// ---------------------------------------------------------------------------
#define AROWS_SM   80
#define ABUF_BYTES (2 * AROWS_SM * S * 2)           // hi+lo per buffer: 23,040
#define MID_DSM    (2 * 128 * S * 2 + 2 * ABUF_BYTES)   // 82,944

__global__ __launch_bounds__(256, 2)
void mid_kernel(const float* __restrict__ x)
{
    extern __shared__ __align__(16) uint16_t sm_mid[];
    const uint32_t base = smem_u32(sm_mid);
    uint32_t* xh32 = reinterpret_cast<uint32_t*>(sm_mid);
    uint32_t* xl32 = xh32 + 128 * (S / 2);
    const uint32_t xh_b = base;
    const uint32_t xl_b = base + 128 * S * 2;
    const uint32_t a0_b = base + 256 * S * 2;       // buf0 hi; lo at +AROWS_SM*S*2

    const int tid  = threadIdx.x;
    const int w    = tid >> 5;
    const int lane = tid & 31;
    const int g    = lane >> 2;
    const int tig  = lane & 3;
    const int t0   = blockIdx.x * 128;
    const int split = blockIdx.y;
    const int kbase = split * (D_DIM / KSPLIT);

    // ldmatrix per-lane address components
    const int arow = (lane & 7) + ((lane >> 3) & 1) * 8;   // A-frag (x tile)
    const int acol = (lane >> 4) * 8;
    const int brow = (lane & 7) + (lane >> 4) * 8;         // B-frag (A_ext tile)
    const int bcol = ((lane >> 3) & 1) * 8;
    const int brow2 = 64 + (lane & 7);                     // single-tile x2 rows
    const int bcol2 = ((lane >> 3) & 1) * 8;
    const uint32_t axh = xh_b + (uint32_t)(((w * 16 + arow) * S + acol) * 2);
    const uint32_t axl = xl_b + (uint32_t)(((w * 16 + arow) * S + acol) * 2);
    const uint32_t bah  = a0_b + (uint32_t)((brow * S + bcol) * 2);
    const uint32_t bal  = a0_b + (uint32_t)(AROWS_SM * S * 2 + (brow * S + bcol) * 2);
    const uint32_t bah2 = a0_b + (uint32_t)((brow2 * S + bcol2) * 2);
    const uint32_t bal2 = a0_b + (uint32_t)(AROWS_SM * S * 2 + (brow2 * S + bcol2) * 2);

    // staging indices
    const int xr = tid >> 4, xq = tid & 15;       // x: row, float4-col

    // A cp.async op map: 1152 = 2(hl) * 72 rows * 8 uint4-cols
    int cp_hl[5], cp_row[5], cp_c4[5];
    bool cp_on[5];
    #pragma unroll
    for (int p = 0; p < 5; p++) {
        int idx = tid + p * 256;
        cp_on[p] = idx < 1152;
        int hl = idx >= 576 ? 1 : 0;
        int r2 = idx - hl * 576;
        cp_hl[p] = hl;
        cp_row[p] = r2 >> 3;
        cp_c4[p] = r2 & 7;
    }

    const int NCHUNK = (D_DIM / KSPLIT) / 64;     // 16

    // prologue: A(0) cp.async into buf0; x(0) LDG into regs
    {
        const int kq = kbase >> 1;
        #pragma unroll
        for (int p = 0; p < 5; p++) {
            if (cp_on[p]) {
                const uint32_t* src = (cp_hl[p] ? g_Axl[cp_row[p]] : g_Axh[cp_row[p]])
                                      + kq + cp_c4[p] * 4;
                uint32_t dst = a0_b + (uint32_t)(cp_hl[p] * (AROWS_SM * S * 2)
                             + cp_row[p] * (S * 2) + cp_c4[p] * 16);
                CP_ASYNC16(dst, src);
            }
        }
        CP_COMMIT();
    }
    float4 xv[8];
    #pragma unroll
    for (int p = 0; p < 8; p++)
        xv[p] = *reinterpret_cast<const float4*>(
            x + (size_t)(t0 + xr + p * 16) * D_DIM + kbase + xq * 4);

    float acc[9][4] = {};

    for (int c = 0; c < NCHUNK; c++) {
        __syncthreads();   // compute(c-1) done reading x smem & A buf[(c+1)&1]

        // STS x(c) from regs
        #pragma unroll
        for (int p = 0; p < 8; p++) {
            uint32_t h0, l0, h1, l1;
            split2(xv[p].x, xv[p].y, h0, l0);
            split2(xv[p].z, xv[p].w, h1, l1);
            int u = (xr + p * 16) * (S / 2) + xq * 2;
            *reinterpret_cast<uint2*>(&xh32[u]) = make_uint2(h0, h1);
            *reinterpret_cast<uint2*>(&xl32[u]) = make_uint2(l0, l1);
        }

        if (c + 1 < NCHUNK) {
            // issue A(c+1) cp.async into buf[(c+1)&1]
            const int kq = (kbase + (c + 1) * 64) >> 1;
            const uint32_t bufo = (uint32_t)(((c + 1) & 1) * ABUF_BYTES);
            #pragma unroll
            for (int p = 0; p < 5; p++) {
                if (cp_on[p]) {
                    const uint32_t* src = (cp_hl[p] ? g_Axl[cp_row[p]] : g_Axh[cp_row[p]])
                                          + kq + cp_c4[p] * 4;
                    uint32_t dst = a0_b + bufo + (uint32_t)(cp_hl[p] * (AROWS_SM * S * 2)
                                 + cp_row[p] * (S * 2) + cp_c4[p] * 16);
                    CP_ASYNC16(dst, src);
                }
            }
            CP_COMMIT();
            // issue x(c+1) LDG into regs (latency overlaps compute(c))
            const int k1 = kbase + (c + 1) * 64;
            #pragma unroll
            for (int p = 0; p < 8; p++)
                xv[p] = *reinterpret_cast<const float4*>(
                    x + (size_t)(t0 + xr + p * 16) * D_DIM + k1 + xq * 4);
            CP_WAIT1();   // A(c) complete; A(c+1) may stay in flight
        } else {
            CP_WAIT0();   // last chunk: A(c) complete
        }
        __syncthreads();

        const uint32_t aoff = (uint32_t)((c & 1) * ABUF_BYTES);
        #pragma unroll
        for (int ks = 0; ks < 4; ks++) {
            const uint32_t kb = (uint32_t)(ks * 32);   // 16 halves
            uint32_t ah0, ah1, ah2, ah3, al0, al1, al2, al3;
            LDSM_X4(ah0, ah1, ah2, ah3, axh + kb);
            LDSM_X4(al0, al1, al2, al3, axl + kb);
            #pragma unroll
            for (int ntp = 0; ntp < 4; ntp++) {        // tile pairs 0..7
                const uint32_t bo = (uint32_t)(ntp * 16 * S * 2) + kb + aoff;
                uint32_t bh0, bh1, bh2, bh3, bl0, bl1, bl2, bl3;
                LDSM_X4(bh0, bh1, bh2, bh3, bah + bo);
                LDSM_X4(bl0, bl1, bl2, bl3, bal + bo);
                mma_bf16(acc[2 * ntp],     ah0, ah1, ah2, ah3, bh0, bh1);
                mma_bf16(acc[2 * ntp],     ah0, ah1, ah2, ah3, bl0, bl1);
                mma_bf16(acc[2 * ntp],     al0, al1, al2, al3, bh0, bh1);
                mma_bf16(acc[2 * ntp + 1], ah0, ah1, ah2, ah3, bh2, bh3);
                mma_bf16(acc[2 * ntp + 1], ah0, ah1, ah2, ah3, bl2, bl3);
                mma_bf16(acc[2 * ntp + 1], al0, al1, al2, al3, bh2, bh3);
            }
            {   // single tile 8 (cols 64..71, incl. router logits)
                uint32_t bh0, bh1, bl0, bl1;
                LDSM_X2(bh0, bh1, bah2 + kb + aoff);
                LDSM_X2(bl0, bl1, bal2 + kb + aoff);
                mma_bf16(acc[8], ah0, ah1, ah2, ah3, bh0, bh1);
                mma_bf16(acc[8], ah0, ah1, ah2, ah3, bl0, bl1);
                mma_bf16(acc[8], al0, al1, al2, al3, bh0, bh1);
            }
        }
    }

    const int r0 = t0 + w * 16 + g;
    #pragma unroll
    for (int nt = 0; nt < 9; nt++) {
        int col = nt * 8 + 2 * tig;
        *reinterpret_cast<float2*>(&g_midp[split][r0][col]) =
            make_float2(acc[nt][0], acc[nt][1]);
        *reinterpret_cast<float2*>(&g_midp[split][r0 + 8][col]) =
            make_float2(acc[nt][2], acc[nt][3]);
    }
}

// ---------------------------------------------------------------------------
// comb: gates (one lane per token + shfl broadcast) + gmid -> bf16 hi/lo.
// ---------------------------------------------------------------------------
__global__ __launch_bounds__(256)
void comb_kernel(int T)
{
    int idx = blockIdx.x * blockDim.x + threadIdx.x;
    if (idx >= T * 16) return;
    int t = idx >> 4;
    int j = idx & 15;
    int lane = threadIdx.x & 31;

    float g1 = 0.f, g2 = 0.f;
    int i1 = 0, i2 = 0;
    if ((lane & 15) == 0) {
        float l[4];
        #pragma unroll
        for (int e = 0; e < 4; e++) {
            float s = 0.f;
            #pragma unroll
            for (int p = 0; p < KSPLIT; p++) s += g_midp[p][t][64 + e];
            l[e] = s;
        }
        i1 = 0; float v1 = l[0];
        if (l[1] > v1) { v1 = l[1]; i1 = 1; }
        if (l[2] > v1) { v1 = l[2]; i1 = 2; }
        if (l[3] > v1) { v1 = l[3]; i1 = 3; }
        float v2 = -3.4e38f;
        #pragma unroll
        for (int e = 0; e < 4; e++)
            if (e != i1 && l[e] > v2) { v2 = l[e]; i2 = e; }
        float e2  = __expf(v2 - v1);
        float inv = 1.0f / (1.0f + e2);
        g1 = LSCALE * inv;
        g2 = LSCALE * e2 * inv;
    }
    const int src = lane & 16;
    i1 = __shfl_sync(0xffffffffu, i1, src);
    i2 = __shfl_sync(0xffffffffu, i2, src);
    g1 = __shfl_sync(0xffffffffu, g1, src);
    g2 = __shfl_sync(0xffffffffu, g2, src);

    int e_mine = j >> 2;
    float gv = (e_mine == i1) ? g1 : (e_mine == i2) ? g2 : 0.f;

    float4 s = make_float4(0.f, 0.f, 0.f, 0.f);
    #pragma unroll
    for (int p = 0; p < KSPLIT; p++) {
        float4 m = *reinterpret_cast<const float4*>(&g_midp[p][t][j * 4]);
        s.x += m.x; s.y += m.y; s.z += m.z; s.w += m.w;
    }
    uint32_t h0, l0, h1, l1;
    split2(s.x * gv, s.y * gv, h0, l0);
    split2(s.z * gv, s.w * gv, h1, l1);
    *reinterpret_cast<uint2*>(&g_Gh[t][j * 2]) = make_uint2(h0, h1);
    *reinterpret_cast<uint2*>(&g_Gl[t][j * 2]) = make_uint2(l0, l1);
}

// ---------------------------------------------------------------------------
// out: out = gmid @ Bf^T, 128x64 CTA tile, K=64 single shot.
//   Warp grid 4x2: each warp 32 rows x 32 cols (2 m-tiles x 4 n-tiles)
//   -> 32 accs/thread, regs ~75 -> 3 CTAs/SM (occ 22% -> ~34%).
//   smem: gh|gl (128 x S) + bh|bl (64 x S) = 55,296 B.
//   grid (O/64, T/128), 256 thr.
// ---------------------------------------------------------------------------
#define OUT_DSM ((2 * 128 + 2 * 64) * S * 2)

__global__ __launch_bounds__(256, 3)
void out_kernel(float* __restrict__ out)
{
    extern __shared__ __align__(16) uint16_t sm_out[];
    const uint32_t base = smem_u32(sm_out);
    uint32_t* gh32 = reinterpret_cast<uint32_t*>(sm_out);
    uint32_t* gl32 = gh32 + 128 * (S / 2);
    uint32_t* bh32 = gl32 + 128 * (S / 2);
    uint32_t* bl32 = bh32 + 64 * (S / 2);
    const uint32_t gh_b = base;
    const uint32_t gl_b = base + 128 * S * 2;
    const uint32_t bh_b = base + 256 * S * 2;
    const uint32_t bl_b = base + (256 + 64) * S * 2;

    const int tid  = threadIdx.x;
    const int w    = tid >> 5;
    const int lane = tid & 31;
    const int g    = lane >> 2;
    const int tig  = lane & 3;
    const int wm   = w & 3;          // warp row-group: rows wm*32..+31
    const int wn   = w >> 2;         // warp col-group: cols wn*32..+31
    const int n0   = blockIdx.x * 64;
    const int t0   = blockIdx.y * 128;

    // stage G tiles (128 rows) + B tiles (64 rows) via uint4
    #pragma unroll
    for (int p = 0; p < 4; p++) {
        int idx = tid + p * 256;        // 0..1023
        int row = idx >> 3;
        int q   = idx & 7;
        int u   = row * (S / 2) + q * 4;
        *reinterpret_cast<uint4*>(&gh32[u]) =
            *reinterpret_cast<const uint4*>(&g_Gh[t0 + row][q * 4]);
        *reinterpret_cast<uint4*>(&gl32[u]) =
            *reinterpret_cast<const uint4*>(&g_Gl[t0 + row][q * 4]);
    }
    #pragma unroll
    for (int p = 0; p < 2; p++) {
        int idx = tid + p * 256;        // 0..511
        int row = idx >> 3;             // 0..63
        int q   = idx & 7;
        int u   = row * (S / 2) + q * 4;
        *reinterpret_cast<uint4*>(&bh32[u]) =
            *reinterpret_cast<const uint4*>(&g_Bh[n0 + row][q * 4]);
        *reinterpret_cast<uint4*>(&bl32[u]) =
            *reinterpret_cast<const uint4*>(&g_Bl[n0 + row][q * 4]);
    }
    __syncthreads();

    // ldmatrix lane-address components
    const int arow = (lane & 7) + ((lane >> 3) & 1) * 8;   // A frag (G tile)
    const int acol = (lane >> 4) * 8;
    const int brow = (lane & 7) + (lane >> 4) * 8;         // B frag (Bf tile)
    const int bcol = ((lane >> 3) & 1) * 8;
    // A frag bases for the warp's 2 m-tiles
    uint32_t agh[2], agl[2];
    #pragma unroll
    for (int mt = 0; mt < 2; mt++) {
        int r = wm * 32 + mt * 16 + arow;
        agh[mt] = gh_b + (uint32_t)((r * S + acol) * 2);
        agl[mt] = gl_b + (uint32_t)((r * S + acol) * 2);
    }
    // B frag base for the warp's 32-col group
    const uint32_t bbh = bh_b + (uint32_t)(((wn * 32 + brow) * S + bcol) * 2);
    const uint32_t bbl = bl_b + (uint32_t)(((wn * 32 + brow) * S + bcol) * 2);

    float acc[2][4][4] = {};

    #pragma unroll
    for (int ks = 0; ks < 4; ks++) {
        const uint32_t kb = (uint32_t)(ks * 32);
        uint32_t ah[2][4], al[2][4];
        #pragma unroll
        for (int mt = 0; mt < 2; mt++) {
            LDSM_X4(ah[mt][0], ah[mt][1], ah[mt][2], ah[mt][3], agh[mt] + kb);
            LDSM_X4(al[mt][0], al[mt][1], al[mt][2], al[mt][3], agl[mt] + kb);
        }
        #pragma unroll
        for (int pr = 0; pr < 2; pr++) {               // n-tile pairs
            const uint32_t bo = (uint32_t)(pr * 16 * S * 2) + kb;
            uint32_t bh0, bh1, bh2, bh3, bl0, bl1, bl2, bl3;
            LDSM_X4(bh0, bh1, bh2, bh3, bbh + bo);
            LDSM_X4(bl0, bl1, bl2, bl3, bbl + bo);
            #pragma unroll
            for (int mt = 0; mt < 2; mt++) {
                mma_bf16(acc[mt][2 * pr],     ah[mt][0], ah[mt][1], ah[mt][2], ah[mt][3], bh0, bh1);
                mma_bf16(acc[mt][2 * pr],     ah[mt][0], ah[mt][1], ah[mt][2], ah[mt][3], bl0, bl1);
                mma_bf16(acc[mt][2 * pr],     al[mt][0], al[mt][1], al[mt][2], al[mt][3], bh0, bh1);
                mma_bf16(acc[mt][2 * pr + 1], ah[mt][0], ah[mt][1], ah[mt][2], ah[mt][3], bh2, bh3);
                mma_bf16(acc[mt][2 * pr + 1], ah[mt][0], ah[mt][1], ah[mt][2], ah[mt][3], bl2, bl3);
                mma_bf16(acc[mt][2 * pr + 1], al[mt][0], al[mt][1], al[mt][2], al[mt][3], bh2, bh3);
            }
        }
    }

    #pragma unroll
    for (int mt = 0; mt < 2; mt++) {
        const int r0 = t0 + wm * 32 + mt * 16 + g;
        #pragma unroll
        for (int nt = 0; nt < 4; nt++) {
            int col = n0 + wn * 32 + nt * 8 + 2 * tig;
            *reinterpret_cast<float2*>(out + (size_t)r0 * O_DIM + col) =
                make_float2(acc[mt][nt][0], acc[mt][nt][1]);
            *reinterpret_cast<float2*>(out + (size_t)(r0 + 8) * O_DIM + col) =
                make_float2(acc[mt][nt][2], acc[mt][nt][3]);
        }
    }
}

// ---------------------------------------------------------------------------
// launch
// ---------------------------------------------------------------------------
extern "C" void kernel_launch(void* const* d_in, const int* in_sizes, int n_in,
                              void* d_out, int out_size)
{
    const float* x  = (const float*)d_in[0];   // (T, D)
    const float* rw = (const float*)d_in[1];   // (E, D)
    const float* A  = (const float*)d_in[2];   // (E, R, D) == (64, D)
    const float* B  = (const float*)d_in[3];   // (E, O, R)
    float* out = (float*)d_out;                // (T, O)

    int T = in_sizes[0] / D_DIM;               // 8192

    cudaFuncSetAttribute(mid_kernel, cudaFuncAttributeMaxDynamicSharedMemorySize, MID_DSM);
    cudaFuncSetAttribute(out_kernel, cudaFuncAttributeMaxDynamicSharedMemorySize, OUT_DSM);

    prep_kernel<<<288 + 16, 256>>>(A, rw, B);
    mid_kernel<<<dim3(T / 128, KSPLIT), 256, MID_DSM>>>(x);
    comb_kernel<<<(T * 16 + 255) / 256, 256>>>(T);
    out_kernel<<<dim3(O_DIM / 64, T / 128), 256, OUT_DSM>>>(out);
}

// round 14
// speedup vs baseline: 1.0073x; 1.0073x over previous
#include <cuda_runtime.h>
#include <cuda_bf16.h>
#include <cstdint>

// ---------------------------------------------------------------------------
// MoE LoRA delta via mma.sync bf16 hi/lo split, smem-staged ldmatrix feeds.
//   x (T=8192, D=4096) f32, router_w (4, D), A (4,16,D), B (4,4096,16)
// P = Xh*Wh + Xh*Wl + Xl*Wh  (fp32 accum)  -> rel_err ~1e-5
// Pipeline:
//   prep  : A_ext + B -> bf16 hi/lo u32 (merged); zero bucket counters
//   mid   : midp[split] = x @ A_ext^T  (sw-pipelined LDG + cp.async dbl-buf A)
//   comb  : gates + bucket tokens by expert PAIR (6 buckets) and compact
//           gmid to K=32 (only the two ACTIVE expert blocks) -> bf16 hi/lo
//   out   : per-bucket out = gmidc @ Bf_pair^T (K=32! half the HMMA),
//           rowmap scatter store.  Zero blocks contributed exact +0 before,
//           so output is bit-identical to the dense version.
// ---------------------------------------------------------------------------

#define D_DIM   4096
#define O_DIM   4096
#define MAXT    8192
#define LSCALE  4.0f
#define KSPLIT  4
#define NROWS   72            // 64 lora + 4 router + 4 pad (9 n-tiles)
#define KU      (D_DIM / 2)   // u32 per A_ext row
#define S       72            // mid smem row stride in bf16 halves (144 B)
#define P32     20            // out smem row pitch in u32 (80 B, conflict-free)

// ------------------------- device scratch (static) -------------------------
__device__ float    g_midp[KSPLIT][MAXT][NROWS];    // 9.4 MB
__device__ uint32_t g_Axh[NROWS][KU];               // 0.58 MB
__device__ uint32_t g_Axl[NROWS][KU];
__device__ uint32_t g_Bh[O_DIM][32];                // 0.5 MB
__device__ uint32_t g_Bl[O_DIM][32];
__device__ uint32_t g_Gch[6 * MAXT][16];            // 3 MB compacted gmid hi
__device__ uint32_t g_Gcl[6 * MAXT][16];            // 3 MB compacted gmid lo
__device__ int      g_rowmap[6 * MAXT];             // 192 KB
__device__ int      g_cnt[6];

__device__ const int c_pairs[6][2] = {{0,1},{0,2},{0,3},{1,2},{1,3},{2,3}};

// ------------------------------ helpers ------------------------------------
static __device__ __forceinline__ uint32_t smem_u32(const void* p) {
    uint32_t a;
    asm("{ .reg .u64 t; cvta.to.shared.u64 t, %1; cvt.u32.u64 %0, t; }"
        : "=r"(a) : "l"(p));
    return a;
}
// fast split: hi = rn-bf16 pair (1 cvt), lo = rn-bf16 of exact residuals
static __device__ __forceinline__ void split2(float a, float b,
                                              uint32_t& hi, uint32_t& lo) {
    uint32_t h;
    asm("cvt.rn.bf16x2.f32 %0, %1, %2;" : "=r"(h) : "f"(b), "f"(a));
    float ahf = __uint_as_float(h << 16);
    float bhf = __uint_as_float(h & 0xFFFF0000u);
    float al = a - ahf;
    float bl = b - bhf;
    uint32_t l;
    asm("cvt.rn.bf16x2.f32 %0, %1, %2;" : "=r"(l) : "f"(bl), "f"(al));
    hi = h; lo = l;
}
static __device__ __forceinline__ void mma_bf16(float* c,
        uint32_t a0, uint32_t a1, uint32_t a2, uint32_t a3,
        uint32_t b0, uint32_t b1) {
    asm volatile(
        "mma.sync.aligned.m16n8k16.row.col.f32.bf16.bf16.f32 "
        "{%0,%1,%2,%3},{%4,%5,%6,%7},{%8,%9},{%0,%1,%2,%3};"
        : "+f"(c[0]), "+f"(c[1]), "+f"(c[2]), "+f"(c[3])
        : "r"(a0), "r"(a1), "r"(a2), "r"(a3), "r"(b0), "r"(b1));
}
#define LDSM_X4(d0, d1, d2, d3, a)                                           \
    asm volatile("ldmatrix.sync.aligned.m8n8.x4.shared.b16 {%0,%1,%2,%3}, [%4];" \
                 : "=r"(d0), "=r"(d1), "=r"(d2), "=r"(d3) : "r"(a))
#define LDSM_X2(d0, d1, a)                                                   \
    asm volatile("ldmatrix.sync.aligned.m8n8.x2.shared.b16 {%0,%1}, [%2];"   \
                 : "=r"(d0), "=r"(d1) : "r"(a))
#define CP_ASYNC16(dst, src)                                                 \
    asm volatile("cp.async.cg.shared.global [%0], [%1], 16;"                 \
                 :: "r"(dst), "l"(src) : "memory")
#define CP_COMMIT() asm volatile("cp.async.commit_group;" ::: "memory")
#define CP_WAIT1()  asm volatile("cp.async.wait_group 1;" ::: "memory")
#define CP_WAIT0()  asm volatile("cp.async.wait_group 0;" ::: "memory")

// ---------------------------------------------------------------------------
// prep: [0,288): A_ext -> g_Ax{h,l};  [288,304): B -> g_B{h,l};  304: zero cnt
// ---------------------------------------------------------------------------
__global__ __launch_bounds__(256)
void prep_kernel(const float* __restrict__ A, const float* __restrict__ rw,
                 const float* __restrict__ B)
{
    int bid = blockIdx.x;
    if (bid == 304) {
        if (threadIdx.x < 6) g_cnt[threadIdx.x] = 0;
        return;
    }
    if (bid < 288) {
        int idx = bid * 256 + threadIdx.x;     // < NROWS * 1024
        int row = idx >> 10;
        int q   = idx & 1023;
        float4 v = make_float4(0.f, 0.f, 0.f, 0.f);
        if (row < 64)
            v = *reinterpret_cast<const float4*>(A + (size_t)row * D_DIM + q * 4);
        else if (row < 68)
            v = *reinterpret_cast<const float4*>(rw + (size_t)(row - 64) * D_DIM + q * 4);
        uint32_t h0, l0, h1, l1;
        split2(v.x, v.y, h0, l0);
        split2(v.z, v.w, h1, l1);
        *reinterpret_cast<uint2*>(&g_Axh[row][q * 2]) = make_uint2(h0, h1);
        *reinterpret_cast<uint2*>(&g_Axl[row][q * 2]) = make_uint2(l0, l1);
    } else {
        int o = (bid - 288) * 256 + threadIdx.x;
        if (o >= O_DIM) return;
        #pragma unroll
        for (int e = 0; e < 4; e++) {
            const float4* src = reinterpret_cast<const float4*>(
                B + ((size_t)e * O_DIM + o) * 16);
            #pragma unroll
            for (int i = 0; i < 4; i++) {
                float4 v = src[i];
                uint32_t h0, l0, h1, l1;
                split2(v.x, v.y, h0, l0);
                split2(v.z, v.w, h1, l1);
                *reinterpret_cast<uint2*>(&g_Bh[o][e * 8 + i * 2]) = make_uint2(h0, h1);
                *reinterpret_cast<uint2*>(&g_Bl[o][e * 8 + i * 2]) = make_uint2(l0, l1);
            }
        }
    }
}

// ---------------------------------------------------------------------------
// mid: midp[split] = x @ A_ext^T.  (unchanged from 117.4us winner)
// ---------------------------------------------------------------------------
#define AROWS_SM   80
#define ABUF_BYTES (2 * AROWS_SM * S * 2)
#define MID_DSM    (2 * 128 * S * 2 + 2 * ABUF_BYTES)   // 82,944

__global__ __launch_bounds__(256, 2)
void mid_kernel(const float* __restrict__ x)
{
    extern __shared__ __align__(16) uint16_t sm_mid[];
    const uint32_t base = smem_u32(sm_mid);
    uint32_t* xh32 = reinterpret_cast<uint32_t*>(sm_mid);
    uint32_t* xl32 = xh32 + 128 * (S / 2);
    const uint32_t xh_b = base;
    const uint32_t xl_b = base + 128 * S * 2;
    const uint32_t a0_b = base + 256 * S * 2;

    const int tid  = threadIdx.x;
    const int w    = tid >> 5;
    const int lane = tid & 31;
    const int g    = lane >> 2;
    const int tig  = lane & 3;
    const int t0   = blockIdx.x * 128;
    const int split = blockIdx.y;
    const int kbase = split * (D_DIM / KSPLIT);

    const int arow = (lane & 7) + ((lane >> 3) & 1) * 8;
    const int acol = (lane >> 4) * 8;
    const int brow = (lane & 7) + (lane >> 4) * 8;
    const int bcol = ((lane >> 3) & 1) * 8;
    const int brow2 = 64 + (lane & 7);
    const int bcol2 = ((lane >> 3) & 1) * 8;
    const uint32_t axh = xh_b + (uint32_t)(((w * 16 + arow) * S + acol) * 2);
    const uint32_t axl = xl_b + (uint32_t)(((w * 16 + arow) * S + acol) * 2);
    const uint32_t bah  = a0_b + (uint32_t)((brow * S + bcol) * 2);
    const uint32_t bal  = a0_b + (uint32_t)(AROWS_SM * S * 2 + (brow * S + bcol) * 2);
    const uint32_t bah2 = a0_b + (uint32_t)((brow2 * S + bcol2) * 2);
    const uint32_t bal2 = a0_b + (uint32_t)(AROWS_SM * S * 2 + (brow2 * S + bcol2) * 2);

    const int xr = tid >> 4, xq = tid & 15;

    int cp_hl[5], cp_row[5], cp_c4[5];
    bool cp_on[5];
    #pragma unroll
    for (int p = 0; p < 5; p++) {
        int idx = tid + p * 256;
        cp_on[p] = idx < 1152;
        int hl = idx >= 576 ? 1 : 0;
        int r2 = idx - hl * 576;
        cp_hl[p] = hl;
        cp_row[p] = r2 >> 3;
        cp_c4[p] = r2 & 7;
    }

    const int NCHUNK = (D_DIM / KSPLIT) / 64;

    {
        const int kq = kbase >> 1;
        #pragma unroll
        for (int p = 0; p < 5; p++) {
            if (cp_on[p]) {
                const uint32_t* src = (cp_hl[p] ? g_Axl[cp_row[p]] : g_Axh[cp_row[p]])
                                      + kq + cp_c4[p] * 4;
                uint32_t dst = a0_b + (uint32_t)(cp_hl[p] * (AROWS_SM * S * 2)
                             + cp_row[p] * (S * 2) + cp_c4[p] * 16);
                CP_ASYNC16(dst, src);
            }
        }
        CP_COMMIT();
    }
    float4 xv[8];
    #pragma unroll
    for (int p = 0; p < 8; p++)
        xv[p] = *reinterpret_cast<const float4*>(
            x + (size_t)(t0 + xr + p * 16) * D_DIM + kbase + xq * 4);

    float acc[9][4] = {};

    for (int c = 0; c < NCHUNK; c++) {
        __syncthreads();

        #pragma unroll
        for (int p = 0; p < 8; p++) {
            uint32_t h0, l0, h1, l1;
            split2(xv[p].x, xv[p].y, h0, l0);
            split2(xv[p].z, xv[p].w, h1, l1);
            int u = (xr + p * 16) * (S / 2) + xq * 2;
            *reinterpret_cast<uint2*>(&xh32[u]) = make_uint2(h0, h1);
            *reinterpret_cast<uint2*>(&xl32[u]) = make_uint2(l0, l1);
        }

        if (c + 1 < NCHUNK) {
            const int kq = (kbase + (c + 1) * 64) >> 1;
            const uint32_t bufo = (uint32_t)(((c + 1) & 1) * ABUF_BYTES);
            #pragma unroll
            for (int p = 0; p < 5; p++) {
                if (cp_on[p]) {
                    const uint32_t* src = (cp_hl[p] ? g_Axl[cp_row[p]] : g_Axh[cp_row[p]])
                                          + kq + cp_c4[p] * 4;
                    uint32_t dst = a0_b + bufo + (uint32_t)(cp_hl[p] * (AROWS_SM * S * 2)
                                 + cp_row[p] * (S * 2) + cp_c4[p] * 16);
                    CP_ASYNC16(dst, src);
                }
            }
            CP_COMMIT();
            const int k1 = kbase + (c + 1) * 64;
            #pragma unroll
            for (int p = 0; p < 8; p++)
                xv[p] = *reinterpret_cast<const float4*>(
                    x + (size_t)(t0 + xr + p * 16) * D_DIM + k1 + xq * 4);
            CP_WAIT1();
        } else {
            CP_WAIT0();
        }
        __syncthreads();

        const uint32_t aoff = (uint32_t)((c & 1) * ABUF_BYTES);
        #pragma unroll
        for (int ks = 0; ks < 4; ks++) {
            const uint32_t kb = (uint32_t)(ks * 32);
            uint32_t ah0, ah1, ah2, ah3, al0, al1, al2, al3;
            LDSM_X4(ah0, ah1, ah2, ah3, axh + kb);
            LDSM_X4(al0, al1, al2, al3, axl + kb);
            #pragma unroll
            for (int ntp = 0; ntp < 4; ntp++) {
                const uint32_t bo = (uint32_t)(ntp * 16 * S * 2) + kb + aoff;
                uint32_t bh0, bh1, bh2, bh3, bl0, bl1, bl2, bl3;
                LDSM_X4(bh0, bh1, bh2, bh3, bah + bo);
                LDSM_X4(bl0, bl1, bl2, bl3, bal + bo);
                mma_bf16(acc[2 * ntp],     ah0, ah1, ah2, ah3, bh0, bh1);
                mma_bf16(acc[2 * ntp],     ah0, ah1, ah2, ah3, bl0, bl1);
                mma_bf16(acc[2 * ntp],     al0, al1, al2, al3, bh0, bh1);
                mma_bf16(acc[2 * ntp + 1], ah0, ah1, ah2, ah3, bh2, bh3);
                mma_bf16(acc[2 * ntp + 1], ah0, ah1, ah2, ah3, bl2, bl3);
                mma_bf16(acc[2 * ntp + 1], al0, al1, al2, al3, bh2, bh3);
            }
            {
                uint32_t bh0, bh1, bl0, bl1;
                LDSM_X2(bh0, bh1, bah2 + kb + aoff);
                LDSM_X2(bl0, bl1, bal2 + kb + aoff);
                mma_bf16(acc[8], ah0, ah1, ah2, ah3, bh0, bh1);
                mma_bf16(acc[8], ah0, ah1, ah2, ah3, bl0, bl1);
                mma_bf16(acc[8], al0, al1, al2, al3, bh0, bh1);
            }
        }
    }

    const int r0 = t0 + w * 16 + g;
    #pragma unroll
    for (int nt = 0; nt < 9; nt++) {
        int col = nt * 8 + 2 * tig;
        *reinterpret_cast<float2*>(&g_midp[split][r0][col]) =
            make_float2(acc[nt][0], acc[nt][1]);
        *reinterpret_cast<float2*>(&g_midp[split][r0 + 8][col]) =
            make_float2(acc[nt][2], acc[nt][3]);
    }
}

// ---------------------------------------------------------------------------
// comb: gates + pair bucketing + K=32 compaction.  32 tokens per 256-thr CTA.
// ---------------------------------------------------------------------------
__global__ __launch_bounds__(256)
void comb_kernel(int T)
{
    __shared__ int   hist[6], basep[6];
    __shared__ int   s_pid[32], s_my[32], s_m[32], s_M[32];
    __shared__ float s_gm[32], s_gM[32];

    const int tid = threadIdx.x;
    if (tid < 6) hist[tid] = 0;
    __syncthreads();

    const int tb = blockIdx.x * 32;
    if (tid < 32) {
        int t = tb + tid;
        float l[4];
        #pragma unroll
        for (int e = 0; e < 4; e++) {
            float s = 0.f;
            #pragma unroll
            for (int p = 0; p < KSPLIT; p++) s += g_midp[p][t][64 + e];
            l[e] = s;
        }
        int i1 = 0; float v1 = l[0];
        if (l[1] > v1) { v1 = l[1]; i1 = 1; }
        if (l[2] > v1) { v1 = l[2]; i1 = 2; }
        if (l[3] > v1) { v1 = l[3]; i1 = 3; }
        int i2 = 0; float v2 = -3.4e38f;
        #pragma unroll
        for (int e = 0; e < 4; e++)
            if (e != i1 && l[e] > v2) { v2 = l[e]; i2 = e; }
        float e2  = __expf(v2 - v1);
        float inv = 1.0f / (1.0f + e2);
        float g1 = LSCALE * inv;
        float g2 = LSCALE * e2 * inv;
        int m = i1 < i2 ? i1 : i2;
        int M = i1 < i2 ? i2 : i1;
        int pid = (m == 0) ? (M - 1) : (m == 1) ? (M + 1) : 5;
        s_pid[tid] = pid;
        s_m[tid]   = m;
        s_M[tid]   = M;
        s_gm[tid]  = (m == i1) ? g1 : g2;
        s_gM[tid]  = (M == i1) ? g1 : g2;
        s_my[tid]  = atomicAdd(&hist[pid], 1);
    }
    __syncthreads();
    if (tid < 6) basep[tid] = atomicAdd(&g_cnt[tid], hist[tid]);
    __syncthreads();

    const int tt = tid >> 3;        // token in block
    const int q  = tid & 7;         // u32-col pair index (of 8)
    const int t  = tb + tt;
    const int pid = s_pid[tt];
    const int pos = basep[pid] + s_my[tt];
    const int slot = q >> 2, qq = q & 3;
    const int e  = slot ? s_M[tt] : s_m[tt];
    const float gv = slot ? s_gM[tt] : s_gm[tt];

    float4 s = make_float4(0.f, 0.f, 0.f, 0.f);
    #pragma unroll
    for (int p = 0; p < KSPLIT; p++) {
        float4 mv = *reinterpret_cast<const float4*>(&g_midp[p][t][e * 16 + qq * 4]);
        s.x += mv.x; s.y += mv.y; s.z += mv.z; s.w += mv.w;
    }
    uint32_t h0, l0, h1, l1;
    split2(s.x * gv, s.y * gv, h0, l0);
    split2(s.z * gv, s.w * gv, h1, l1);
    const size_t rr = (size_t)pid * MAXT + pos;
    *reinterpret_cast<uint2*>(&g_Gch[rr][q * 2]) = make_uint2(h0, h1);
    *reinterpret_cast<uint2*>(&g_Gcl[rr][q * 2]) = make_uint2(l0, l1);
    if (q == 0) g_rowmap[rr] = t;
}

// ---------------------------------------------------------------------------
// out: per-bucket out = gmidc @ Bf_pair^T, 128x128 tile, K=32 (2 ksteps).
//   grid (O/128, 64 m-tiles, 6 buckets); empty tiles early-exit.
//   warps 4x2: 32 rows x 64 cols each.  Rowmap-predicated scatter store.
//   static smem 41.5 KB -> 2 CTAs/SM.
// ---------------------------------------------------------------------------
__global__ __launch_bounds__(256, 2)
void out_kernel(float* __restrict__ out)
{
    __shared__ uint32_t gh[128][P32];
    __shared__ uint32_t gl[128][P32];
    __shared__ uint32_t bh[128][P32];
    __shared__ uint32_t bl[128][P32];
    __shared__ int      rms[128];

    const int pid = blockIdx.z;
    const int cnt = g_cnt[pid];
    const int m0  = blockIdx.y * 128;
    if (m0 >= cnt) return;
    const int n0  = blockIdx.x * 128;
    const int em  = c_pairs[pid][0];
    const int eM  = c_pairs[pid][1];

    const int tid  = threadIdx.x;
    const int w    = tid >> 5;
    const int lane = tid & 31;
    const int g    = lane >> 2;
    const int tig  = lane & 3;
    const int wm   = w & 3;          // rows wm*32..+31
    const int wn   = w >> 2;         // cols wn*64..+63

    // stage G (predicated zeros beyond cnt): 512 uint4 per array
    #pragma unroll
    for (int p = 0; p < 2; p++) {
        int idx = tid + p * 256;     // 0..511
        int row = idx >> 2;
        int q4  = idx & 3;
        int gr  = m0 + row;
        uint4 vh = make_uint4(0u, 0u, 0u, 0u);
        uint4 vl = make_uint4(0u, 0u, 0u, 0u);
        if (gr < cnt) {
            const size_t rr = (size_t)pid * MAXT + gr;
            vh = *reinterpret_cast<const uint4*>(&g_Gch[rr][q4 * 4]);
            vl = *reinterpret_cast<const uint4*>(&g_Gcl[rr][q4 * 4]);
        }
        *reinterpret_cast<uint4*>(&gh[row][q4 * 4]) = vh;
        *reinterpret_cast<uint4*>(&gl[row][q4 * 4]) = vl;
    }
    if (tid < 128) {
        int gr = m0 + tid;
        rms[tid] = (gr < cnt) ? g_rowmap[(size_t)pid * MAXT + gr] : -1;
    }
    // stage B: k-cols = block em (u32 0..7) then eM (8..15)
    #pragma unroll
    for (int p = 0; p < 2; p++) {
        int idx = tid + p * 256;
        int row = idx >> 2;
        int q4  = idx & 3;
        int e   = (q4 < 2) ? em : eM;
        int qq  = q4 & 1;
        uint4 vh = *reinterpret_cast<const uint4*>(&g_Bh[n0 + row][e * 8 + qq * 4]);
        uint4 vl = *reinterpret_cast<const uint4*>(&g_Bl[n0 + row][e * 8 + qq * 4]);
        *reinterpret_cast<uint4*>(&bh[row][q4 * 4]) = vh;
        *reinterpret_cast<uint4*>(&bl[row][q4 * 4]) = vl;
    }
    __syncthreads();

    const uint32_t gh_b = smem_u32(gh);
    const uint32_t gl_b = smem_u32(gl);
    const uint32_t bh_b = smem_u32(bh);
    const uint32_t bl_b = smem_u32(bl);
    const uint32_t PB = P32 * 4;   // 80 B pitch

    const int arow = (lane & 7) + ((lane >> 3) & 1) * 8;
    const int acol = (lane >> 4) * 8;              // halves
    const int brow = (lane & 7) + (lane >> 4) * 8;
    const int bcol = ((lane >> 3) & 1) * 8;
    uint32_t agh[2], agl[2];
    #pragma unroll
    for (int mt = 0; mt < 2; mt++) {
        uint32_t off = (uint32_t)((wm * 32 + mt * 16 + arow) * PB + acol * 2);
        agh[mt] = gh_b + off;
        agl[mt] = gl_b + off;
    }
    const uint32_t boff = (uint32_t)((wn * 64 + brow) * PB + bcol * 2);
    const uint32_t bbh = bh_b + boff;
    const uint32_t bbl = bl_b + boff;

    float acc[2][8][4] = {};

    #pragma unroll
    for (int ks = 0; ks < 2; ks++) {               // K = 32
        const uint32_t kb = (uint32_t)(ks * 32);
        uint32_t ah[2][4], al[2][4];
        #pragma unroll
        for (int mt = 0; mt < 2; mt++) {
            LDSM_X4(ah[mt][0], ah[mt][1], ah[mt][2], ah[mt][3], agh[mt] + kb);
            LDSM_X4(al[mt][0], al[mt][1], al[mt][2], al[mt][3], agl[mt] + kb);
        }
        #pragma unroll
        for (int pr = 0; pr < 4; pr++) {           // 8 n-tiles in pairs
            const uint32_t bo = (uint32_t)(pr * 16 * PB) + kb;
            uint32_t bh0, bh1, bh2, bh3, bl0, bl1, bl2, bl3;
            LDSM_X4(bh0, bh1, bh2, bh3, bbh + bo);
            LDSM_X4(bl0, bl1, bl2, bl3, bbl + bo);
            #pragma unroll
            for (int mt = 0; mt < 2; mt++) {
                mma_bf16(acc[mt][2 * pr],     ah[mt][0], ah[mt][1], ah[mt][2], ah[mt][3], bh0, bh1);
                mma_bf16(acc[mt][2 * pr],     ah[mt][0], ah[mt][1], ah[mt][2], ah[mt][3], bl0, bl1);
                mma_bf16(acc[mt][2 * pr],     al[mt][0], al[mt][1], al[mt][2], al[mt][3], bh0, bh1);
                mma_bf16(acc[mt][2 * pr + 1], ah[mt][0], ah[mt][1], ah[mt][2], ah[mt][3], bh2, bh3);
                mma_bf16(acc[mt][2 * pr + 1], ah[mt][0], ah[mt][1], ah[mt][2], ah[mt][3], bl2, bl3);
                mma_bf16(acc[mt][2 * pr + 1], al[mt][0], al[mt][1], al[mt][2], al[mt][3], bh2, bh3);
            }
        }
    }

    #pragma unroll
    for (int mt = 0; mt < 2; mt++) {
        const int lr0 = wm * 32 + mt * 16 + g;
        const int rm0 = rms[lr0];
        const int rm1 = rms[lr0 + 8];
        #pragma unroll
        for (int nt = 0; nt < 8; nt++) {
            int col = n0 + wn * 64 + nt * 8 + 2 * tig;
            if (rm0 >= 0)
                *reinterpret_cast<float2*>(out + (size_t)rm0 * O_DIM + col) =
                    make_float2(acc[mt][nt][0], acc[mt][nt][1]);
            if (rm1 >= 0)
                *reinterpret_cast<float2*>(out + (size_t)rm1 * O_DIM + col) =
                    make_float2(acc[mt][nt][2], acc[mt][nt][3]);
        }
    }
}

// ---------------------------------------------------------------------------
// launch
// ---------------------------------------------------------------------------
extern "C" void kernel_launch(void* const* d_in, const int* in_sizes, int n_in,
                              void* d_out, int out_size)
{
    const float* x  = (const float*)d_in[0];   // (T, D)
    const float* rw = (const float*)d_in[1];   // (E, D)
    const float* A  = (const float*)d_in[2];   // (E, R, D) == (64, D)
    const float* B  = (const float*)d_in[3];   // (E, O, R)
    float* out = (float*)d_out;                // (T, O)

    int T = in_sizes[0] / D_DIM;               // 8192

    cudaFuncSetAttribute(mid_kernel, cudaFuncAttributeMaxDynamicSharedMemorySize, MID_DSM);

    prep_kernel<<<305, 256>>>(A, rw, B);
    mid_kernel<<<dim3(T / 128, KSPLIT), 256, MID_DSM>>>(x);
    comb_kernel<<<T / 32, 256>>>(T);
    out_kernel<<<dim3(O_DIM / 128, T / 128, 6), 256>>>(out);
}

// round 16
// speedup vs baseline: 1.2184x; 1.2096x over previous
#include <cuda_runtime.h>
#include <cuda_fp16.h>
#include <cstdint>

// ---------------------------------------------------------------------------
// MoE LoRA delta via mma.sync fp16 2-pass split, smem-staged ldmatrix feeds.
//   x (T=8192, D=4096) f32, router_w (4, D), A (4,16,D), B (4,4096,16)
// P = Xh*(Wh + Wl), fp16 rn split of W only  -> rel_err ~2-4e-4 (< 1e-3)
// (fp16 mantissa 11 bits: dropped X-residual term ~2^-11 relative)
// Pipeline:
//   prep  : A_ext = [A(64); router_w(4); 0(8)] + B -> fp16 hi/lo u32 (merged)
//   mid   : midp[split] = x @ A_ext^T  (x staged fp16-hi only; cp.async A)
//   comb  : gates (top-2 softmax * 4.0, shfl-shared) + gmid -> fp16 (single)
//   out   : out = gmid @ Bf^T  (K=64, 128x128 tile, 2 passes: G*(Bh+Bl))
// ---------------------------------------------------------------------------

#define D_DIM   4096
#define O_DIM   4096
#define MAXT    8192
#define LSCALE  4.0f
#define KSPLIT  4
#define NROWS   72            // 64 lora + 4 router + 4 pad (9 n-tiles)
#define KU      (D_DIM / 2)   // u32 per A_ext row
#define S       72            // smem row stride in fp16 halves (144 B)

// ------------------------- device scratch (static) -------------------------
__device__ float    g_midp[KSPLIT][MAXT][NROWS];    // 9.4 MB
__device__ uint32_t g_Axh[NROWS][KU];               // fp16 hi
__device__ uint32_t g_Axl[NROWS][KU];               // fp16 lo (W residual)
__device__ uint32_t g_Bh[O_DIM][32];
__device__ uint32_t g_Bl[O_DIM][32];
__device__ uint32_t g_Gh[MAXT][32];                 // fp16 gmid (single)

// ------------------------------ helpers ------------------------------------
static __device__ __forceinline__ uint32_t smem_u32(const void* p) {
    uint32_t a;
    asm("{ .reg .u64 t; cvta.to.shared.u64 t, %1; cvt.u32.u64 %0, t; }"
        : "=r"(a) : "l"(p));
    return a;
}
// pack two f32 -> f16x2 (a in low half)
static __device__ __forceinline__ uint32_t cvt2h(float a, float b) {
    uint32_t h;
    asm("cvt.rn.f16x2.f32 %0, %1, %2;" : "=r"(h) : "f"(b), "f"(a));
    return h;
}
// full split: hi = rn-f16 pair, lo = rn-f16 of exact residuals
static __device__ __forceinline__ void split2h(float a, float b,
                                               uint32_t& hi, uint32_t& lo) {
    uint32_t h;
    asm("cvt.rn.f16x2.f32 %0, %1, %2;" : "=r"(h) : "f"(b), "f"(a));
    float ahf, bhf;
    asm("{ .reg .f16 x, y; mov.b32 {x, y}, %2; "
        "cvt.f32.f16 %0, x; cvt.f32.f16 %1, y; }"
        : "=f"(ahf), "=f"(bhf) : "r"(h));
    float al = a - ahf, bl = b - bhf;
    uint32_t l;
    asm("cvt.rn.f16x2.f32 %0, %1, %2;" : "=r"(l) : "f"(bl), "f"(al));
    hi = h; lo = l;
}
static __device__ __forceinline__ void mma_f16(float* c,
        uint32_t a0, uint32_t a1, uint32_t a2, uint32_t a3,
        uint32_t b0, uint32_t b1) {
    asm volatile(
        "mma.sync.aligned.m16n8k16.row.col.f32.f16.f16.f32 "
        "{%0,%1,%2,%3},{%4,%5,%6,%7},{%8,%9},{%0,%1,%2,%3};"
        : "+f"(c[0]), "+f"(c[1]), "+f"(c[2]), "+f"(c[3])
        : "r"(a0), "r"(a1), "r"(a2), "r"(a3), "r"(b0), "r"(b1));
}
#define LDSM_X4(d0, d1, d2, d3, a)                                           \
    asm volatile("ldmatrix.sync.aligned.m8n8.x4.shared.b16 {%0,%1,%2,%3}, [%4];" \
                 : "=r"(d0), "=r"(d1), "=r"(d2), "=r"(d3) : "r"(a))
#define LDSM_X2(d0, d1, a)                                                   \
    asm volatile("ldmatrix.sync.aligned.m8n8.x2.shared.b16 {%0,%1}, [%2];"   \
                 : "=r"(d0), "=r"(d1) : "r"(a))
#define CP_ASYNC16(dst, src)                                                 \
    asm volatile("cp.async.cg.shared.global [%0], [%1], 16;"                 \
                 :: "r"(dst), "l"(src) : "memory")
#define CP_COMMIT() asm volatile("cp.async.commit_group;" ::: "memory")
#define CP_WAIT1()  asm volatile("cp.async.wait_group 1;" ::: "memory")
#define CP_WAIT0()  asm volatile("cp.async.wait_group 0;" ::: "memory")

// ---------------------------------------------------------------------------
// prep (merged): blocks [0,288): A_ext -> g_Ax{h,l};  [288,304): B -> g_B{h,l}
// ---------------------------------------------------------------------------
__global__ __launch_bounds__(256)
void prep_kernel(const float* __restrict__ A, const float* __restrict__ rw,
                 const float* __restrict__ B)
{
    int bid = blockIdx.x;
    if (bid < 288) {
        int idx = bid * 256 + threadIdx.x;     // < NROWS * 1024
        int row = idx >> 10;
        int q   = idx & 1023;
        float4 v = make_float4(0.f, 0.f, 0.f, 0.f);
        if (row < 64)
            v = *reinterpret_cast<const float4*>(A + (size_t)row * D_DIM + q * 4);
        else if (row < 68)
            v = *reinterpret_cast<const float4*>(rw + (size_t)(row - 64) * D_DIM + q * 4);
        uint32_t h0, l0, h1, l1;
        split2h(v.x, v.y, h0, l0);
        split2h(v.z, v.w, h1, l1);
        *reinterpret_cast<uint2*>(&g_Axh[row][q * 2]) = make_uint2(h0, h1);
        *reinterpret_cast<uint2*>(&g_Axl[row][q * 2]) = make_uint2(l0, l1);
    } else {
        int o = (bid - 288) * 256 + threadIdx.x;
        if (o >= O_DIM) return;
        #pragma unroll
        for (int e = 0; e < 4; e++) {
            const float4* src = reinterpret_cast<const float4*>(
                B + ((size_t)e * O_DIM + o) * 16);
            #pragma unroll
            for (int i = 0; i < 4; i++) {
                float4 v = src[i];
                uint32_t h0, l0, h1, l1;
                split2h(v.x, v.y, h0, l0);
                split2h(v.z, v.w, h1, l1);
                *reinterpret_cast<uint2*>(&g_Bh[o][e * 8 + i * 2]) = make_uint2(h0, h1);
                *reinterpret_cast<uint2*>(&g_Bl[o][e * 8 + i * 2]) = make_uint2(l0, l1);
            }
        }
    }
}

// ---------------------------------------------------------------------------
// mid: midp[split] = x @ A_ext^T.  grid (T/128, KSPLIT), 256 thr.
//   x staged fp16-HI only (residual dropped); A hi+lo cp.async dbl-buffered.
//   2 passes per kstep: Xh*Awh + Xh*Awl.  smem 64.5 KB.
// ---------------------------------------------------------------------------
#define AROWS_SM   80
#define ABUF_BYTES (2 * AROWS_SM * S * 2)           // hi+lo per buffer: 23,040
#define MID_DSM    (128 * S * 2 + 2 * ABUF_BYTES)   // 64,512

__global__ __launch_bounds__(256, 2)
void mid_kernel(const float* __restrict__ x)
{
    extern __shared__ __align__(16) uint16_t sm_mid[];
    const uint32_t base = smem_u32(sm_mid);
    uint32_t* xh32 = reinterpret_cast<uint32_t*>(sm_mid);
    const uint32_t xh_b = base;
    const uint32_t a0_b = base + 128 * S * 2;       // buf0 hi; lo at +AROWS_SM*S*2

    const int tid  = threadIdx.x;
    const int w    = tid >> 5;
    const int lane = tid & 31;
    const int g    = lane >> 2;
    const int tig  = lane & 3;
    const int t0   = blockIdx.x * 128;
    const int split = blockIdx.y;
    const int kbase = split * (D_DIM / KSPLIT);

    // ldmatrix per-lane address components
    const int arow = (lane & 7) + ((lane >> 3) & 1) * 8;   // A-frag (x tile)
    const int acol = (lane >> 4) * 8;
    const int brow = (lane & 7) + (lane >> 4) * 8;         // B-frag (A_ext tile)
    const int bcol = ((lane >> 3) & 1) * 8;
    const int brow2 = 64 + (lane & 7);                     // single-tile x2 rows
    const int bcol2 = ((lane >> 3) & 1) * 8;
    const uint32_t axh = xh_b + (uint32_t)(((w * 16 + arow) * S + acol) * 2);
    const uint32_t bah  = a0_b + (uint32_t)((brow * S + bcol) * 2);
    const uint32_t bal  = a0_b + (uint32_t)(AROWS_SM * S * 2 + (brow * S + bcol) * 2);
    const uint32_t bah2 = a0_b + (uint32_t)((brow2 * S + bcol2) * 2);
    const uint32_t bal2 = a0_b + (uint32_t)(AROWS_SM * S * 2 + (brow2 * S + bcol2) * 2);

    // staging indices
    const int xr = tid >> 4, xq = tid & 15;       // x: row, float4-col

    // A cp.async op map: 1152 = 2(hl) * 72 rows * 8 uint4-cols
    int cp_hl[5], cp_row[5], cp_c4[5];
    bool cp_on[5];
    #pragma unroll
    for (int p = 0; p < 5; p++) {
        int idx = tid + p * 256;
        cp_on[p] = idx < 1152;
        int hl = idx >= 576 ? 1 : 0;
        int r2 = idx - hl * 576;
        cp_hl[p] = hl;
        cp_row[p] = r2 >> 3;
        cp_c4[p] = r2 & 7;
    }

    const int NCHUNK = (D_DIM / KSPLIT) / 64;     // 16

    // prologue: A(0) cp.async into buf0; x(0) LDG into regs
    {
        const int kq = kbase >> 1;
        #pragma unroll
        for (int p = 0; p < 5; p++) {
            if (cp_on[p]) {
                const uint32_t* src = (cp_hl[p] ? g_Axl[cp_row[p]] : g_Axh[cp_row[p]])
                                      + kq + cp_c4[p] * 4;
                uint32_t dst = a0_b + (uint32_t)(cp_hl[p] * (AROWS_SM * S * 2)
                             + cp_row[p] * (S * 2) + cp_c4[p] * 16);
                CP_ASYNC16(dst, src);
            }
        }
        CP_COMMIT();
    }
    float4 xv[8];
    #pragma unroll
    for (int p = 0; p < 8; p++)
        xv[p] = *reinterpret_cast<const float4*>(
            x + (size_t)(t0 + xr + p * 16) * D_DIM + kbase + xq * 4);

    float acc[9][4] = {};

    for (int c = 0; c < NCHUNK; c++) {
        __syncthreads();   // compute(c-1) done reading x smem & A buf[(c+1)&1]

        // STS x(c) hi from regs
        #pragma unroll
        for (int p = 0; p < 8; p++) {
            uint32_t h0 = cvt2h(xv[p].x, xv[p].y);
            uint32_t h1 = cvt2h(xv[p].z, xv[p].w);
            int u = (xr + p * 16) * (S / 2) + xq * 2;
            *reinterpret_cast<uint2*>(&xh32[u]) = make_uint2(h0, h1);
        }

        if (c + 1 < NCHUNK) {
            // issue A(c+1) cp.async into buf[(c+1)&1]
            const int kq = (kbase + (c + 1) * 64) >> 1;
            const uint32_t bufo = (uint32_t)(((c + 1) & 1) * ABUF_BYTES);
            #pragma unroll
            for (int p = 0; p < 5; p++) {
                if (cp_on[p]) {
                    const uint32_t* src = (cp_hl[p] ? g_Axl[cp_row[p]] : g_Axh[cp_row[p]])
                                          + kq + cp_c4[p] * 4;
                    uint32_t dst = a0_b + bufo + (uint32_t)(cp_hl[p] * (AROWS_SM * S * 2)
                                 + cp_row[p] * (S * 2) + cp_c4[p] * 16);
                    CP_ASYNC16(dst, src);
                }
            }
            CP_COMMIT();
            // issue x(c+1) LDG into regs (latency overlaps compute(c))
            const int k1 = kbase + (c + 1) * 64;
            #pragma unroll
            for (int p = 0; p < 8; p++)
                xv[p] = *reinterpret_cast<const float4*>(
                    x + (size_t)(t0 + xr + p * 16) * D_DIM + k1 + xq * 4);
            CP_WAIT1();   // A(c) complete; A(c+1) may stay in flight
        } else {
            CP_WAIT0();   // last chunk: A(c) complete
        }
        __syncthreads();

        const uint32_t aoff = (uint32_t)((c & 1) * ABUF_BYTES);
        #pragma unroll
        for (int ks = 0; ks < 4; ks++) {
            const uint32_t kb = (uint32_t)(ks * 32);   // 16 halves
            uint32_t ah0, ah1, ah2, ah3;
            LDSM_X4(ah0, ah1, ah2, ah3, axh + kb);
            #pragma unroll
            for (int ntp = 0; ntp < 4; ntp++) {        // tile pairs 0..7
                const uint32_t bo = (uint32_t)(ntp * 16 * S * 2) + kb + aoff;
                uint32_t bh0, bh1, bh2, bh3, bl0, bl1, bl2, bl3;
                LDSM_X4(bh0, bh1, bh2, bh3, bah + bo);
                LDSM_X4(bl0, bl1, bl2, bl3, bal + bo);
                mma_f16(acc[2 * ntp],     ah0, ah1, ah2, ah3, bh0, bh1);
                mma_f16(acc[2 * ntp],     ah0, ah1, ah2, ah3, bl0, bl1);
                mma_f16(acc[2 * ntp + 1], ah0, ah1, ah2, ah3, bh2, bh3);
                mma_f16(acc[2 * ntp + 1], ah0, ah1, ah2, ah3, bl2, bl3);
            }
            {   // single tile 8 (cols 64..71, incl. router logits)
                uint32_t bh0, bh1, bl0, bl1;
                LDSM_X2(bh0, bh1, bah2 + kb + aoff);
                LDSM_X2(bl0, bl1, bal2 + kb + aoff);
                mma_f16(acc[8], ah0, ah1, ah2, ah3, bh0, bh1);
                mma_f16(acc[8], ah0, ah1, ah2, ah3, bl0, bl1);
            }
        }
    }

    const int r0 = t0 + w * 16 + g;
    #pragma unroll
    for (int nt = 0; nt < 9; nt++) {
        int col = nt * 8 + 2 * tig;
        *reinterpret_cast<float2*>(&g_midp[split][r0][col]) =
            make_float2(acc[nt][0], acc[nt][1]);
        *reinterpret_cast<float2*>(&g_midp[split][r0 + 8][col]) =
            make_float2(acc[nt][2], acc[nt][3]);
    }
}

// ---------------------------------------------------------------------------
// comb: gates (one lane per token + shfl broadcast) + gmid -> single fp16.
// ---------------------------------------------------------------------------
__global__ __launch_bounds__(256)
void comb_kernel(int T)
{
    int idx = blockIdx.x * blockDim.x + threadIdx.x;
    if (idx >= T * 16) return;
    int t = idx >> 4;
    int j = idx & 15;
    int lane = threadIdx.x & 31;

    float g1 = 0.f, g2 = 0.f;
    int i1 = 0, i2 = 0;
    if ((lane & 15) == 0) {
        float l[4];
        #pragma unroll
        for (int e = 0; e < 4; e++) {
            float s = 0.f;
            #pragma unroll
            for (int p = 0; p < KSPLIT; p++) s += g_midp[p][t][64 + e];
            l[e] = s;
        }
        i1 = 0; float v1 = l[0];
        if (l[1] > v1) { v1 = l[1]; i1 = 1; }
        if (l[2] > v1) { v1 = l[2]; i1 = 2; }
        if (l[3] > v1) { v1 = l[3]; i1 = 3; }
        float v2 = -3.4e38f;
        #pragma unroll
        for (int e = 0; e < 4; e++)
            if (e != i1 && l[e] > v2) { v2 = l[e]; i2 = e; }
        float e2  = __expf(v2 - v1);
        float inv = 1.0f / (1.0f + e2);
        g1 = LSCALE * inv;
        g2 = LSCALE * e2 * inv;
    }
    const int src = lane & 16;
    i1 = __shfl_sync(0xffffffffu, i1, src);
    i2 = __shfl_sync(0xffffffffu, i2, src);
    g1 = __shfl_sync(0xffffffffu, g1, src);
    g2 = __shfl_sync(0xffffffffu, g2, src);

    int e_mine = j >> 2;
    float gv = (e_mine == i1) ? g1 : (e_mine == i2) ? g2 : 0.f;

    float4 s = make_float4(0.f, 0.f, 0.f, 0.f);
    #pragma unroll
    for (int p = 0; p < KSPLIT; p++) {
        float4 m = *reinterpret_cast<const float4*>(&g_midp[p][t][j * 4]);
        s.x += m.x; s.y += m.y; s.z += m.z; s.w += m.w;
    }
    uint32_t h0 = cvt2h(s.x * gv, s.y * gv);
    uint32_t h1 = cvt2h(s.z * gv, s.w * gv);
    *reinterpret_cast<uint2*>(&g_Gh[t][j * 2]) = make_uint2(h0, h1);
}

// ---------------------------------------------------------------------------
// out: out = gmid @ Bf^T, 128x128 CTA tile, K=64 single shot, 2 passes.
//   Warp grid 4x2: each warp 32 rows x 64 cols (2 m-tiles x 8 n-tiles).
//   smem: gh + bh + bl (each 128 x S) = 55.3 KB.  grid (O/128, T/128).
// ---------------------------------------------------------------------------
#define OUT_DSM (3 * 128 * S * 2)

__global__ __launch_bounds__(256, 2)
void out_kernel(float* __restrict__ out)
{
    extern __shared__ __align__(16) uint16_t sm_out[];
    const uint32_t base = smem_u32(sm_out);
    uint32_t* gh32 = reinterpret_cast<uint32_t*>(sm_out);
    uint32_t* bh32 = gh32 + 128 * (S / 2);
    uint32_t* bl32 = bh32 + 128 * (S / 2);
    const uint32_t gh_b = base;
    const uint32_t bh_b = base + 128 * S * 2;
    const uint32_t bl_b = base + 256 * S * 2;

    const int tid  = threadIdx.x;
    const int w    = tid >> 5;
    const int lane = tid & 31;
    const int g    = lane >> 2;
    const int tig  = lane & 3;
    const int wm   = w & 3;          // warp row-group: rows wm*32..+31
    const int wn   = w >> 2;         // warp col-group: cols wn*64..+63
    const int n0   = blockIdx.x * 128;
    const int t0   = blockIdx.y * 128;

    // stage three tiles via uint4 (12 LDG.128 + 12 STS.128 per thread)
    #pragma unroll
    for (int p = 0; p < 4; p++) {
        int idx = tid + p * 256;        // 0..1023
        int row = idx >> 3;
        int q   = idx & 7;
        int u   = row * (S / 2) + q * 4;
        *reinterpret_cast<uint4*>(&gh32[u]) =
            *reinterpret_cast<const uint4*>(&g_Gh[t0 + row][q * 4]);
        *reinterpret_cast<uint4*>(&bh32[u]) =
            *reinterpret_cast<const uint4*>(&g_Bh[n0 + row][q * 4]);
        *reinterpret_cast<uint4*>(&bl32[u]) =
            *reinterpret_cast<const uint4*>(&g_Bl[n0 + row][q * 4]);
    }
    __syncthreads();

    // ldmatrix lane-address components
    const int arow = (lane & 7) + ((lane >> 3) & 1) * 8;
    const int acol = (lane >> 4) * 8;
    const int brow = (lane & 7) + (lane >> 4) * 8;
    const int bcol = ((lane >> 3) & 1) * 8;
    uint32_t agh[2];
    #pragma unroll
    for (int mt = 0; mt < 2; mt++) {
        int r = wm * 32 + mt * 16 + arow;
        agh[mt] = gh_b + (uint32_t)((r * S + acol) * 2);
    }
    const uint32_t bbh = bh_b + (uint32_t)(((wn * 64 + brow) * S + bcol) * 2);
    const uint32_t bbl = bl_b + (uint32_t)(((wn * 64 + brow) * S + bcol) * 2);

    float acc[2][8][4] = {};

    #pragma unroll
    for (int ks = 0; ks < 4; ks++) {
        const uint32_t kb = (uint32_t)(ks * 32);
        uint32_t ah[2][4];
        #pragma unroll
        for (int mt = 0; mt < 2; mt++)
            LDSM_X4(ah[mt][0], ah[mt][1], ah[mt][2], ah[mt][3], agh[mt] + kb);
        #pragma unroll
        for (int pr = 0; pr < 4; pr++) {               // n-tile pairs
            const uint32_t bo = (uint32_t)(pr * 16 * S * 2) + kb;
            uint32_t bh0, bh1, bh2, bh3, bl0, bl1, bl2, bl3;
            LDSM_X4(bh0, bh1, bh2, bh3, bbh + bo);
            LDSM_X4(bl0, bl1, bl2, bl3, bbl + bo);
            #pragma unroll
            for (int mt = 0; mt < 2; mt++) {
                mma_f16(acc[mt][2 * pr],     ah[mt][0], ah[mt][1], ah[mt][2], ah[mt][3], bh0, bh1);
                mma_f16(acc[mt][2 * pr],     ah[mt][0], ah[mt][1], ah[mt][2], ah[mt][3], bl0, bl1);
                mma_f16(acc[mt][2 * pr + 1], ah[mt][0], ah[mt][1], ah[mt][2], ah[mt][3], bh2, bh3);
                mma_f16(acc[mt][2 * pr + 1], ah[mt][0], ah[mt][1], ah[mt][2], ah[mt][3], bl2, bl3);
            }
        }
    }

    #pragma unroll
    for (int mt = 0; mt < 2; mt++) {
        const int r0 = t0 + wm * 32 + mt * 16 + g;
        #pragma unroll
        for (int nt = 0; nt < 8; nt++) {
            int col = n0 + wn * 64 + nt * 8 + 2 * tig;
            *reinterpret_cast<float2*>(out + (size_t)r0 * O_DIM + col) =
                make_float2(acc[mt][nt][0], acc[mt][nt][1]);
            *reinterpret_cast<float2*>(out + (size_t)(r0 + 8) * O_DIM + col) =
                make_float2(acc[mt][nt][2], acc[mt][nt][3]);
        }
    }
}

// ---------------------------------------------------------------------------
// launch
// ---------------------------------------------------------------------------
extern "C" void kernel_launch(void* const* d_in, const int* in_sizes, int n_in,
                              void* d_out, int out_size)
{
    const float* x  = (const float*)d_in[0];   // (T, D)
    const float* rw = (const float*)d_in[1];   // (E, D)
    const float* A  = (const float*)d_in[2];   // (E, R, D) == (64, D)
    const float* B  = (const float*)d_in[3];   // (E, O, R)
    float* out = (float*)d_out;                // (T, O)

    int T = in_sizes[0] / D_DIM;               // 8192

    cudaFuncSetAttribute(mid_kernel, cudaFuncAttributeMaxDynamicSharedMemorySize, MID_DSM);
    cudaFuncSetAttribute(out_kernel, cudaFuncAttributeMaxDynamicSharedMemorySize, OUT_DSM);

    prep_kernel<<<304, 256>>>(A, rw, B);
    mid_kernel<<<dim3(T / 128, KSPLIT), 256, MID_DSM>>>(x);
    comb_kernel<<<(T * 16 + 255) / 256, 256>>>(T);
    out_kernel<<<dim3(O_DIM / 128, T / 128), 256, OUT_DSM>>>(out);
}

// round 17
// speedup vs baseline: 1.5306x; 1.2563x over previous
#include <cuda_runtime.h>
#include <cuda_fp16.h>
#include <cstdint>

// ---------------------------------------------------------------------------
// MoE LoRA delta via single-pass fp16 mma.sync, smem-staged ldmatrix feeds.
//   x (T=8192, D=4096) f32, router_w (4, D), A (4,16,D), B (4,4096,16)
// All operands rn-quantized to fp16, fp32 accumulate.
// 4 independent quantization sources (X, A, G, B) each ~2.3e-4 ->
// predicted rel_err ~4.6e-4 (< 1e-3).
// Pipeline:
//   prep  : A_ext = [A(64); router_w(4); 0(8)] + B -> fp16 u32 (merged)
//   mid   : midp[split] = x @ A_ext^T  (single pass; cp.async dbl-buf A)
//   comb  : gates (top-2 softmax * 4.0, shfl-shared) + gmid -> fp16
//   out   : out = gmid @ Bf^T  (K=64, 128x128 tile, single pass)
// ---------------------------------------------------------------------------

#define D_DIM   4096
#define O_DIM   4096
#define MAXT    8192
#define LSCALE  4.0f
#define KSPLIT  4
#define NROWS   72            // 64 lora + 4 router + 4 pad (9 n-tiles)
#define KU      (D_DIM / 2)   // u32 per A_ext row
#define S       72            // smem row stride in fp16 halves (144 B)

// ------------------------- device scratch (static) -------------------------
__device__ float    g_midp[KSPLIT][MAXT][NROWS];    // 9.4 MB
__device__ uint32_t g_Axh[NROWS][KU];               // fp16 A_ext
__device__ uint32_t g_Bh[O_DIM][32];                // fp16 Bf
__device__ uint32_t g_Gh[MAXT][32];                 // fp16 gmid

// ------------------------------ helpers ------------------------------------
static __device__ __forceinline__ uint32_t smem_u32(const void* p) {
    uint32_t a;
    asm("{ .reg .u64 t; cvta.to.shared.u64 t, %1; cvt.u32.u64 %0, t; }"
        : "=r"(a) : "l"(p));
    return a;
}
// pack two f32 -> f16x2 (a in low half)
static __device__ __forceinline__ uint32_t cvt2h(float a, float b) {
    uint32_t h;
    asm("cvt.rn.f16x2.f32 %0, %1, %2;" : "=r"(h) : "f"(b), "f"(a));
    return h;
}
static __device__ __forceinline__ void mma_f16(float* c,
        uint32_t a0, uint32_t a1, uint32_t a2, uint32_t a3,
        uint32_t b0, uint32_t b1) {
    asm volatile(
        "mma.sync.aligned.m16n8k16.row.col.f32.f16.f16.f32 "
        "{%0,%1,%2,%3},{%4,%5,%6,%7},{%8,%9},{%0,%1,%2,%3};"
        : "+f"(c[0]), "+f"(c[1]), "+f"(c[2]), "+f"(c[3])
        : "r"(a0), "r"(a1), "r"(a2), "r"(a3), "r"(b0), "r"(b1));
}
#define LDSM_X4(d0, d1, d2, d3, a)                                           \
    asm volatile("ldmatrix.sync.aligned.m8n8.x4.shared.b16 {%0,%1,%2,%3}, [%4];" \
                 : "=r"(d0), "=r"(d1), "=r"(d2), "=r"(d3) : "r"(a))
#define LDSM_X2(d0, d1, a)                                                   \
    asm volatile("ldmatrix.sync.aligned.m8n8.x2.shared.b16 {%0,%1}, [%2];"   \
                 : "=r"(d0), "=r"(d1) : "r"(a))
#define CP_ASYNC16(dst, src)                                                 \
    asm volatile("cp.async.cg.shared.global [%0], [%1], 16;"                 \
                 :: "r"(dst), "l"(src) : "memory")
#define CP_COMMIT() asm volatile("cp.async.commit_group;" ::: "memory")
#define CP_WAIT1()  asm volatile("cp.async.wait_group 1;" ::: "memory")
#define CP_WAIT0()  asm volatile("cp.async.wait_group 0;" ::: "memory")

// ---------------------------------------------------------------------------
// prep (merged): blocks [0,288): A_ext -> g_Axh;  [288,304): B -> g_Bh
// ---------------------------------------------------------------------------
__global__ __launch_bounds__(256)
void prep_kernel(const float* __restrict__ A, const float* __restrict__ rw,
                 const float* __restrict__ B)
{
    int bid = blockIdx.x;
    if (bid < 288) {
        int idx = bid * 256 + threadIdx.x;     // < NROWS * 1024
        int row = idx >> 10;
        int q   = idx & 1023;
        float4 v = make_float4(0.f, 0.f, 0.f, 0.f);
        if (row < 64)
            v = *reinterpret_cast<const float4*>(A + (size_t)row * D_DIM + q * 4);
        else if (row < 68)
            v = *reinterpret_cast<const float4*>(rw + (size_t)(row - 64) * D_DIM + q * 4);
        uint32_t h0 = cvt2h(v.x, v.y);
        uint32_t h1 = cvt2h(v.z, v.w);
        *reinterpret_cast<uint2*>(&g_Axh[row][q * 2]) = make_uint2(h0, h1);
    } else {
        int o = (bid - 288) * 256 + threadIdx.x;
        if (o >= O_DIM) return;
        #pragma unroll
        for (int e = 0; e < 4; e++) {
            const float4* src = reinterpret_cast<const float4*>(
                B + ((size_t)e * O_DIM + o) * 16);
            #pragma unroll
            for (int i = 0; i < 4; i++) {
                float4 v = src[i];
                uint32_t h0 = cvt2h(v.x, v.y);
                uint32_t h1 = cvt2h(v.z, v.w);
                *reinterpret_cast<uint2*>(&g_Bh[o][e * 8 + i * 2]) = make_uint2(h0, h1);
            }
        }
    }
}

// ---------------------------------------------------------------------------
// mid: midp[split] = x @ A_ext^T.  grid (T/128, KSPLIT), 256 thr.
//   Single-pass fp16.  A cp.async double-buffered; x LDG sw-pipelined.
//   smem: xh (128 x S) + 2 x ah (80 x S) = 41.5 KB.
// ---------------------------------------------------------------------------
#define AROWS_SM   80
#define ABUF_BYTES (AROWS_SM * S * 2)               // 11,520 per buffer
#define MID_DSM    (128 * S * 2 + 2 * ABUF_BYTES)   // 41,472

__global__ __launch_bounds__(256, 2)
void mid_kernel(const float* __restrict__ x)
{
    extern __shared__ __align__(16) uint16_t sm_mid[];
    const uint32_t base = smem_u32(sm_mid);
    uint32_t* xh32 = reinterpret_cast<uint32_t*>(sm_mid);
    const uint32_t xh_b = base;
    const uint32_t a0_b = base + 128 * S * 2;       // A buf0

    const int tid  = threadIdx.x;
    const int w    = tid >> 5;
    const int lane = tid & 31;
    const int g    = lane >> 2;
    const int tig  = lane & 3;
    const int t0   = blockIdx.x * 128;
    const int split = blockIdx.y;
    const int kbase = split * (D_DIM / KSPLIT);

    // ldmatrix per-lane address components
    const int arow = (lane & 7) + ((lane >> 3) & 1) * 8;   // A-frag (x tile)
    const int acol = (lane >> 4) * 8;
    const int brow = (lane & 7) + (lane >> 4) * 8;         // B-frag (A_ext tile)
    const int bcol = ((lane >> 3) & 1) * 8;
    const int brow2 = 64 + (lane & 7);                     // single-tile x2 rows
    const int bcol2 = ((lane >> 3) & 1) * 8;
    const uint32_t axh  = xh_b + (uint32_t)(((w * 16 + arow) * S + acol) * 2);
    const uint32_t bah  = a0_b + (uint32_t)((brow * S + bcol) * 2);
    const uint32_t bah2 = a0_b + (uint32_t)((brow2 * S + bcol2) * 2);

    // staging indices
    const int xr = tid >> 4, xq = tid & 15;       // x: row, float4-col

    // A cp.async op map: 576 = 72 rows * 8 uint4-cols
    int cp_row[3], cp_c4[3];
    bool cp_on[3];
    #pragma unroll
    for (int p = 0; p < 3; p++) {
        int idx = tid + p * 256;
        cp_on[p] = idx < 576;
        cp_row[p] = idx >> 3;
        cp_c4[p] = idx & 7;
    }

    const int NCHUNK = (D_DIM / KSPLIT) / 64;     // 16

    // prologue: A(0) cp.async into buf0; x(0) LDG into regs
    {
        const int kq = kbase >> 1;
        #pragma unroll
        for (int p = 0; p < 3; p++) {
            if (cp_on[p]) {
                const uint32_t* src = g_Axh[cp_row[p]] + kq + cp_c4[p] * 4;
                uint32_t dst = a0_b + (uint32_t)(cp_row[p] * (S * 2) + cp_c4[p] * 16);
                CP_ASYNC16(dst, src);
            }
        }
        CP_COMMIT();
    }
    float4 xv[8];
    #pragma unroll
    for (int p = 0; p < 8; p++)
        xv[p] = *reinterpret_cast<const float4*>(
            x + (size_t)(t0 + xr + p * 16) * D_DIM + kbase + xq * 4);

    float acc[9][4] = {};

    for (int c = 0; c < NCHUNK; c++) {
        __syncthreads();   // compute(c-1) done reading x smem & A buf[(c+1)&1]

        // STS x(c) from regs
        #pragma unroll
        for (int p = 0; p < 8; p++) {
            uint32_t h0 = cvt2h(xv[p].x, xv[p].y);
            uint32_t h1 = cvt2h(xv[p].z, xv[p].w);
            int u = (xr + p * 16) * (S / 2) + xq * 2;
            *reinterpret_cast<uint2*>(&xh32[u]) = make_uint2(h0, h1);
        }

        if (c + 1 < NCHUNK) {
            // issue A(c+1) cp.async into buf[(c+1)&1]
            const int kq = (kbase + (c + 1) * 64) >> 1;
            const uint32_t bufo = (uint32_t)(((c + 1) & 1) * ABUF_BYTES);
            #pragma unroll
            for (int p = 0; p < 3; p++) {
                if (cp_on[p]) {
                    const uint32_t* src = g_Axh[cp_row[p]] + kq + cp_c4[p] * 4;
                    uint32_t dst = a0_b + bufo
                                 + (uint32_t)(cp_row[p] * (S * 2) + cp_c4[p] * 16);
                    CP_ASYNC16(dst, src);
                }
            }
            CP_COMMIT();
            // issue x(c+1) LDG into regs (latency overlaps compute(c))
            const int k1 = kbase + (c + 1) * 64;
            #pragma unroll
            for (int p = 0; p < 8; p++)
                xv[p] = *reinterpret_cast<const float4*>(
                    x + (size_t)(t0 + xr + p * 16) * D_DIM + k1 + xq * 4);
            CP_WAIT1();   // A(c) complete; A(c+1) may stay in flight
        } else {
            CP_WAIT0();   // last chunk: A(c) complete
        }
        __syncthreads();

        const uint32_t aoff = (uint32_t)((c & 1) * ABUF_BYTES);
        #pragma unroll
        for (int ks = 0; ks < 4; ks++) {
            const uint32_t kb = (uint32_t)(ks * 32);   // 16 halves
            uint32_t ah0, ah1, ah2, ah3;
            LDSM_X4(ah0, ah1, ah2, ah3, axh + kb);
            #pragma unroll
            for (int ntp = 0; ntp < 4; ntp++) {        // tile pairs 0..7
                const uint32_t bo = (uint32_t)(ntp * 16 * S * 2) + kb + aoff;
                uint32_t bh0, bh1, bh2, bh3;
                LDSM_X4(bh0, bh1, bh2, bh3, bah + bo);
                mma_f16(acc[2 * ntp],     ah0, ah1, ah2, ah3, bh0, bh1);
                mma_f16(acc[2 * ntp + 1], ah0, ah1, ah2, ah3, bh2, bh3);
            }
            {   // single tile 8 (cols 64..71, incl. router logits)
                uint32_t bh0, bh1;
                LDSM_X2(bh0, bh1, bah2 + kb + aoff);
                mma_f16(acc[8], ah0, ah1, ah2, ah3, bh0, bh1);
            }
        }
    }

    const int r0 = t0 + w * 16 + g;
    #pragma unroll
    for (int nt = 0; nt < 9; nt++) {
        int col = nt * 8 + 2 * tig;
        *reinterpret_cast<float2*>(&g_midp[split][r0][col]) =
            make_float2(acc[nt][0], acc[nt][1]);
        *reinterpret_cast<float2*>(&g_midp[split][r0 + 8][col]) =
            make_float2(acc[nt][2], acc[nt][3]);
    }
}

// ---------------------------------------------------------------------------
// comb: gates (one lane per token + shfl broadcast) + gmid -> fp16.
// ---------------------------------------------------------------------------
__global__ __launch_bounds__(256)
void comb_kernel(int T)
{
    int idx = blockIdx.x * blockDim.x + threadIdx.x;
    if (idx >= T * 16) return;
    int t = idx >> 4;
    int j = idx & 15;
    int lane = threadIdx.x & 31;

    float g1 = 0.f, g2 = 0.f;
    int i1 = 0, i2 = 0;
    if ((lane & 15) == 0) {
        float l[4];
        #pragma unroll
        for (int e = 0; e < 4; e++) {
            float s = 0.f;
            #pragma unroll
            for (int p = 0; p < KSPLIT; p++) s += g_midp[p][t][64 + e];
            l[e] = s;
        }
        i1 = 0; float v1 = l[0];
        if (l[1] > v1) { v1 = l[1]; i1 = 1; }
        if (l[2] > v1) { v1 = l[2]; i1 = 2; }
        if (l[3] > v1) { v1 = l[3]; i1 = 3; }
        float v2 = -3.4e38f;
        #pragma unroll
        for (int e = 0; e < 4; e++)
            if (e != i1 && l[e] > v2) { v2 = l[e]; i2 = e; }
        float e2  = __expf(v2 - v1);
        float inv = 1.0f / (1.0f + e2);
        g1 = LSCALE * inv;
        g2 = LSCALE * e2 * inv;
    }
    const int src = lane & 16;
    i1 = __shfl_sync(0xffffffffu, i1, src);
    i2 = __shfl_sync(0xffffffffu, i2, src);
    g1 = __shfl_sync(0xffffffffu, g1, src);
    g2 = __shfl_sync(0xffffffffu, g2, src);

    int e_mine = j >> 2;
    float gv = (e_mine == i1) ? g1 : (e_mine == i2) ? g2 : 0.f;

    float4 s = make_float4(0.f, 0.f, 0.f, 0.f);
    #pragma unroll
    for (int p = 0; p < KSPLIT; p++) {
        float4 m = *reinterpret_cast<const float4*>(&g_midp[p][t][j * 4]);
        s.x += m.x; s.y += m.y; s.z += m.z; s.w += m.w;
    }
    uint32_t h0 = cvt2h(s.x * gv, s.y * gv);
    uint32_t h1 = cvt2h(s.z * gv, s.w * gv);
    *reinterpret_cast<uint2*>(&g_Gh[t][j * 2]) = make_uint2(h0, h1);
}

// ---------------------------------------------------------------------------
// out: out = gmid @ Bf^T, 128x128 CTA tile, K=64 single shot, single pass.
//   Warp grid 4x2: each warp 32 rows x 64 cols (2 m-tiles x 8 n-tiles).
//   smem: gh + bh (each 128 x S) = 36.9 KB.  grid (O/128, T/128).
// ---------------------------------------------------------------------------
#define OUT_DSM (2 * 128 * S * 2)

__global__ __launch_bounds__(256, 2)
void out_kernel(float* __restrict__ out)
{
    extern __shared__ __align__(16) uint16_t sm_out[];
    const uint32_t base = smem_u32(sm_out);
    uint32_t* gh32 = reinterpret_cast<uint32_t*>(sm_out);
    uint32_t* bh32 = gh32 + 128 * (S / 2);
    const uint32_t gh_b = base;
    const uint32_t bh_b = base + 128 * S * 2;

    const int tid  = threadIdx.x;
    const int w    = tid >> 5;
    const int lane = tid & 31;
    const int g    = lane >> 2;
    const int tig  = lane & 3;
    const int wm   = w & 3;          // warp row-group: rows wm*32..+31
    const int wn   = w >> 2;         // warp col-group: cols wn*64..+63
    const int n0   = blockIdx.x * 128;
    const int t0   = blockIdx.y * 128;

    // stage two tiles via uint4 (8 LDG.128 + 8 STS.128 per thread)
    #pragma unroll
    for (int p = 0; p < 4; p++) {
        int idx = tid + p * 256;        // 0..1023
        int row = idx >> 3;
        int q   = idx & 7;
        int u   = row * (S / 2) + q * 4;
        *reinterpret_cast<uint4*>(&gh32[u]) =
            *reinterpret_cast<const uint4*>(&g_Gh[t0 + row][q * 4]);
        *reinterpret_cast<uint4*>(&bh32[u]) =
            *reinterpret_cast<const uint4*>(&g_Bh[n0 + row][q * 4]);
    }
    __syncthreads();

    // ldmatrix lane-address components
    const int arow = (lane & 7) + ((lane >> 3) & 1) * 8;
    const int acol = (lane >> 4) * 8;
    const int brow = (lane & 7) + (lane >> 4) * 8;
    const int bcol = ((lane >> 3) & 1) * 8;
    uint32_t agh[2];
    #pragma unroll
    for (int mt = 0; mt < 2; mt++) {
        int r = wm * 32 + mt * 16 + arow;
        agh[mt] = gh_b + (uint32_t)((r * S + acol) * 2);
    }
    const uint32_t bbh = bh_b + (uint32_t)(((wn * 64 + brow) * S + bcol) * 2);

    float acc[2][8][4] = {};

    #pragma unroll
    for (int ks = 0; ks < 4; ks++) {
        const uint32_t kb = (uint32_t)(ks * 32);
        uint32_t ah[2][4];
        #pragma unroll
        for (int mt = 0; mt < 2; mt++)
            LDSM_X4(ah[mt][0], ah[mt][1], ah[mt][2], ah[mt][3], agh[mt] + kb);
        #pragma unroll
        for (int pr = 0; pr < 4; pr++) {               // n-tile pairs
            const uint32_t bo = (uint32_t)(pr * 16 * S * 2) + kb;
            uint32_t bh0, bh1, bh2, bh3;
            LDSM_X4(bh0, bh1, bh2, bh3, bbh + bo);
            #pragma unroll
            for (int mt = 0; mt < 2; mt++) {
                mma_f16(acc[mt][2 * pr],     ah[mt][0], ah[mt][1], ah[mt][2], ah[mt][3], bh0, bh1);
                mma_f16(acc[mt][2 * pr + 1], ah[mt][0], ah[mt][1], ah[mt][2], ah[mt][3], bh2, bh3);
            }
        }
    }

    #pragma unroll
    for (int mt = 0; mt < 2; mt++) {
        const int r0 = t0 + wm * 32 + mt * 16 + g;
        #pragma unroll
        for (int nt = 0; nt < 8; nt++) {
            int col = n0 + wn * 64 + nt * 8 + 2 * tig;
            *reinterpret_cast<float2*>(out + (size_t)r0 * O_DIM + col) =
                make_float2(acc[mt][nt][0], acc[mt][nt][1]);
            *reinterpret_cast<float2*>(out + (size_t)(r0 + 8) * O_DIM + col) =
                make_float2(acc[mt][nt][2], acc[mt][nt][3]);
        }
    }
}

// ---------------------------------------------------------------------------
// launch
// ---------------------------------------------------------------------------
extern "C" void kernel_launch(void* const* d_in, const int* in_sizes, int n_in,
                              void* d_out, int out_size)
{
    const float* x  = (const float*)d_in[0];   // (T, D)
    const float* rw = (const float*)d_in[1];   // (E, D)
    const float* A  = (const float*)d_in[2];   // (E, R, D) == (64, D)
    const float* B  = (const float*)d_in[3];   // (E, O, R)
    float* out = (float*)d_out;                // (T, O)

    int T = in_sizes[0] / D_DIM;               // 8192

    cudaFuncSetAttribute(mid_kernel, cudaFuncAttributeMaxDynamicSharedMemorySize, MID_DSM);
    cudaFuncSetAttribute(out_kernel, cudaFuncAttributeMaxDynamicSharedMemorySize, OUT_DSM);

    prep_kernel<<<304, 256>>>(A, rw, B);
    mid_kernel<<<dim3(T / 128, KSPLIT), 256, MID_DSM>>>(x);
    comb_kernel<<<(T * 16 + 255) / 256, 256>>>(T);
    out_kernel<<<dim3(O_DIM / 128, T / 128), 256, OUT_DSM>>>(out);
}